// round 12
// baseline (speedup 1.0000x reference)
#include <cuda_runtime.h>
#include <cooperative_groups.h>
#include <math.h>
#include <stdint.h>

namespace cg = cooperative_groups;

// ---------------------------------------------------------------------------
// LogNCDE depth-2 log-ODE scan, 4-CTA cluster per batch element (128 CTAs).
// Rank r owns channels {2r,2r+1} and Wv2 rows [128r,128r+128).
// v12 (= v11 with corrected tile geometry): thread t owns row-pair rp=t>>2
// (rows 2rp,2rp+1) and k-quarter kq=t&3. Full-width register tiles:
// w0=16 u64 (2x16k), w1=w2=32 u64 (2x32k). Matvec = reg dot (2-row
// activation reuse) + 2 shfl_xor quad reduce + direct write by kq==0.
// 8 barriers + 2 cluster.syncs per step. Prep kernel computes sigs + h0.
// ---------------------------------------------------------------------------

namespace {
constexpr int kB   = 32;
constexpr int kT   = 2049;
constexpr int kD   = 8;
constexpr int kS   = 64;
constexpr int kH   = 128;
constexpr int kP   = 28;
constexpr int kNW  = 128;
constexpr int kWin = 16;
constexpr int kOut = 8;
constexpr int CL   = 4;
constexpr int NT   = 256;

// shared-memory float offsets (16B aligned)
constexpr int OFF_SIGS  = 0;        // [128][36]
constexpr int OFF_CH    = 4608;     // [128][16]
constexpr int OFF_BV0   = 6656;     // 128
constexpr int OFF_BV1   = 6784;     // 128
constexpr int OFF_BV2S  = 6912;     // 128
constexpr int OFF_WR    = 7040;     // 512
constexpr int OFF_BR    = 7552;     // 16
constexpr int OFF_HH    = 7568;     // [129][64]
constexpr int OFF_Z0    = 15824;    // 128
constexpr int OFF_D0    = 15952;    // 128
constexpr int OFF_Z1    = 16080;    // 128
constexpr int OFF_D1    = 16208;    // 128
constexpr int OFF_V     = 16336;    // 512 (single buffer)
constexpr int OFF_TDS   = 16848;    // 128
constexpr int OFF_WT    = 16976;    // 2 x 64
constexpr int OFF_PT    = 17104;    // 2 x 128
constexpr int OFF_UT    = 17360;    // 2 x 128
constexpr int OFF_RD    = 17616;    // 128
constexpr int OFF_RSLOT = 17744;    // 4 x 64
constexpr int SMEMF     = 18000;    // 72 KB
}  // namespace

__device__ float g_sigs[kB * kNW * 36];   // per-batch window signatures
__device__ float g_h0[kB * kS];           // per-batch initial state

static __device__ const int c_II[kP] =
    {0,0,0,0,0,0,0,1,1,1,1,1,1,2,2,2,2,2,3,3,3,3,4,4,4,5,5,6};
static __device__ const int c_JJ[kP] =
    {1,2,3,4,5,6,7,2,3,4,5,6,7,3,4,5,6,7,4,5,6,7,5,6,7,6,7,7};

using u64t = unsigned long long;

__device__ __forceinline__ int pidx(int i, int j) {   // Lyndon pair index, i<j
    return 7 * i - (i * (i - 1)) / 2 + (j - i - 1);
}
__device__ __forceinline__ u64t ffma2(u64t a, u64t b, u64t c) {
    u64t r;
    asm("fma.rn.f32x2 %0, %1, %2, %3;" : "=l"(r) : "l"(a), "l"(b), "l"(c));
    return r;
}
__device__ __forceinline__ float fold2(u64t a) {
    float lo, hi;
    asm("mov.b64 {%0, %1}, %2;" : "=f"(lo), "=f"(hi) : "l"(a));
    return lo + hi;
}
__device__ __forceinline__ float qsum(float s) {   // quad reduce (kq lanes)
    s += __shfl_xor_sync(0xffffffffu, s, 1);
    s += __shfl_xor_sync(0xffffffffu, s, 2);
    return s;
}
__device__ __forceinline__ float tanh_ap(float x) {
    float r; asm("tanh.approx.f32 %0, %1;" : "=f"(r) : "f"(x)); return r;
}
__device__ __forceinline__ void sp_sg(float s, float& z, float& d) {
    if (s > 20.f) { z = s; d = 1.f; }
    else {
        float e = __expf(s);
        float inv = __frcp_rn(1.f + e);
        z = __logf(1.f + e);
        d = e * inv;
    }
}
__device__ __forceinline__ float sp_f(float x) {   // accurate (one-time h0)
    return (x > 20.f) ? x : log1pf(expf(x));
}

// ======================= prep kernel: signatures + h0 =======================
__global__ __launch_bounds__(128, 1)
void logncde_prep_kernel(
    const float* __restrict__ x,
    const float* __restrict__ Wi0, const float* __restrict__ bi0,
    const float* __restrict__ Wi1, const float* __restrict__ bi1,
    const float* __restrict__ Wi2, const float* __restrict__ bi2)
{
    __shared__ float z0[kH], z1[kH];
    const int b = blockIdx.x;
    const int t = threadIdx.x;

    // depth-2 log-signature, one window per thread
    {
        const float* xb = x + (size_t)b * kT * kD + (size_t)t * kWin * kD;
        float cum[kD], prev[kD], Mm[kD * kD];
        #pragma unroll
        for (int i = 0; i < kD; i++) { cum[i] = 0.f; prev[i] = xb[i]; }
        #pragma unroll
        for (int i = 0; i < kD * kD; i++) Mm[i] = 0.f;
        for (int w = 0; w < kWin; w++) {
            float dl[kD];
            #pragma unroll
            for (int j = 0; j < kD; j++) {
                float c = xb[(w + 1) * kD + j];
                dl[j] = c - prev[j];
                prev[j] = c;
            }
            #pragma unroll
            for (int i = 0; i < kD; i++)
                #pragma unroll
                for (int j = 0; j < kD; j++)
                    Mm[i * kD + j] = fmaf(cum[i], dl[j], Mm[i * kD + j]);
            #pragma unroll
            for (int i = 0; i < kD; i++) cum[i] += dl[i];
        }
        float* sgw = &g_sigs[((size_t)b * kNW + t) * 36];
        #pragma unroll
        for (int i = 0; i < kD; i++) sgw[i] = cum[i];
        #pragma unroll
        for (int p = 0; p < kP; p++) {
            int i = c_II[p], j = c_JJ[p];
            sgw[8 + p] = 0.5f * (Mm[i * kD + j] - Mm[j * kD + i]);
        }
    }

    // initial MLP h0 (accurate path)
    const float* x0 = x + (size_t)b * kT * kD;
    {
        float acc = bi0[t];
        #pragma unroll
        for (int k = 0; k < kD; k++) acc = fmaf(Wi0[t * kD + k], x0[k], acc);
        z0[t] = sp_f(acc);
    }
    __syncthreads();
    {
        float acc = bi1[t];
        #pragma unroll 16
        for (int k = 0; k < kH; k++) acc = fmaf(Wi1[t * kH + k], z0[k], acc);
        z1[t] = sp_f(acc);
    }
    __syncthreads();
    if (t < kS) {
        float acc = bi2[t];
        #pragma unroll 16
        for (int k = 0; k < kH; k++) acc = fmaf(Wi2[t * kH + k], z1[k], acc);
        g_h0[b * kS + t] = acc;
    }
}

// ============================== scan kernel ================================
__global__ __launch_bounds__(NT, 1) __cluster_dims__(CL, 1, 1)
void logncde_v12_kernel(
    const float* __restrict__ Wv0, const float* __restrict__ bv0,
    const float* __restrict__ Wv1, const float* __restrict__ bv1,
    const float* __restrict__ Wv2, const float* __restrict__ bv2,
    const float* __restrict__ Wr,  const float* __restrict__ br,
    float* __restrict__ out)
{
    extern __shared__ float sm[];
    cg::cluster_group cluster = cg::this_cluster();
    const int t    = threadIdx.x;
    const int rank = (int)cluster.block_rank();
    const int b    = blockIdx.x >> 2;
    const int d0g  = 2 * rank;
    const int rp   = t >> 2;     // row-pair 0..63
    const int kq   = t & 3;      // k-quarter
    const int r0   = 2 * rp;
    const int r1   = r0 + 1;

    float* peer[CL - 1];
    #pragma unroll
    for (int p = 1; p < CL; p++)
        peer[p - 1] = cluster.map_shared_rank(sm, (rank + p) & (CL - 1));

    // ---- register weight tiles: 2 rows x k-quarter (FULL width) ----
    // Wv0 row = 64 floats = 16 ull2; quarter = 16 floats = 4 ull2 -> w0[16] u64
    // Wv1/Wv2 row = 128 floats = 32 ull2; quarter = 32 floats = 8 ull2 -> 32 u64
    u64t w0[16], w1[32], w2[32];
    {
        const ulonglong2* W0 = (const ulonglong2*)Wv0;   // row stride 16 ull2
        #pragma unroll
        for (int rr = 0; rr < 2; rr++)
            #pragma unroll
            for (int j = 0; j < 4; j++) {
                ulonglong2 v = W0[(r0 + rr) * 16 + kq * 4 + j];
                w0[rr * 8 + 2 * j]     = v.x;
                w0[rr * 8 + 2 * j + 1] = v.y;
            }
        const ulonglong2* W1 = (const ulonglong2*)Wv1;   // row stride 32 ull2
        #pragma unroll
        for (int rr = 0; rr < 2; rr++)
            #pragma unroll
            for (int j = 0; j < 8; j++) {
                ulonglong2 v = W1[(r0 + rr) * 32 + kq * 8 + j];
                w1[rr * 16 + 2 * j]     = v.x;
                w1[rr * 16 + 2 * j + 1] = v.y;
            }
        const ulonglong2* W2 = (const ulonglong2*)Wv2;   // row stride 32 ull2
        #pragma unroll
        for (int rr = 0; rr < 2; rr++)
            #pragma unroll
            for (int j = 0; j < 8; j++) {
                ulonglong2 v = W2[(kH * rank + r0 + rr) * 32 + kq * 8 + j];
                w2[rr * 16 + 2 * j]     = v.x;
                w2[rr * 16 + 2 * j + 1] = v.y;
            }
    }

    // ---- staging ----
    for (int i = t; i < kH; i += NT) {
        sm[OFF_BV0 + i]  = bv0[i];
        sm[OFF_BV1 + i]  = bv1[i];
        sm[OFF_BV2S + i] = bv2[kH * rank + i];
    }
    for (int i = t; i < kOut * kS; i += NT) sm[OFF_WR + i] = Wr[i];
    if (t < kOut) sm[OFF_BR + t] = br[t];
    {
        const float* src = &g_sigs[(size_t)b * kNW * 36];
        for (int i = t; i < kNW * 36; i += NT) sm[OFF_SIGS + i] = src[i];
    }
    if (t < kS) sm[OFF_HH + t] = g_h0[b * kS + t];
    __syncthreads();

    // ---- precompute C coefficients for all steps (this rank's channels) ----
    for (int i = t; i < kNW * 16; i += NT) {
        int n = i >> 4, j = i & 15;
        int dl = j >> 3, e = j & 7;
        int d = d0g + dl;
        const float* sgn = &sm[OFF_SIGS + n * 36];
        float v = 0.f;
        if (e < d)      v =  sgn[8 + pidx(e, d)];
        else if (e > d) v = -sgn[8 + pidx(d, e)];
        sm[OFF_CH + n * 16 + dl * 8 + e] = v;
    }

    cluster.sync();

    // ============================ scan loop ============================
    for (int n = 0; n < kNW; n++) {

        // --- A: z0 = sp(Wv0 h + bv0)
        {
            const ulonglong2* h2 = (const ulonglong2*)&sm[OFF_HH + n * kS];
            u64t a0 = 0, a1 = 0;
            #pragma unroll
            for (int j = 0; j < 4; j++) {
                ulonglong2 hv = h2[kq * 4 + j];
                a0 = ffma2(w0[2 * j],     hv.x, a0);
                a0 = ffma2(w0[2 * j + 1], hv.y, a0);
                a1 = ffma2(w0[8 + 2 * j],     hv.x, a1);
                a1 = ffma2(w0[8 + 2 * j + 1], hv.y, a1);
            }
            float s0 = qsum(fold2(a0));
            float s1 = qsum(fold2(a1));
            if (kq == 0) {
                float z, d;
                sp_sg(s0 + sm[OFF_BV0 + r0], z, d);
                sm[OFF_Z0 + r0] = z; sm[OFF_D0 + r0] = d;
                sp_sg(s1 + sm[OFF_BV0 + r1], z, d);
                sm[OFF_Z0 + r1] = z; sm[OFF_D0 + r1] = d;
            }
        }
        __syncthreads();

        // --- B: z1 = sp(Wv1 z0 + bv1)
        {
            const ulonglong2* z2 = (const ulonglong2*)&sm[OFF_Z0];
            u64t a0 = 0, a1 = 0;
            #pragma unroll
            for (int j = 0; j < 8; j++) {
                ulonglong2 zv = z2[kq * 8 + j];
                a0 = ffma2(w1[2 * j],     zv.x, a0);
                a0 = ffma2(w1[2 * j + 1], zv.y, a0);
                a1 = ffma2(w1[16 + 2 * j],     zv.x, a1);
                a1 = ffma2(w1[16 + 2 * j + 1], zv.y, a1);
            }
            float s0 = qsum(fold2(a0));
            float s1 = qsum(fold2(a1));
            if (kq == 0) {
                float z, d;
                sp_sg(s0 + sm[OFF_BV1 + r0], z, d);
                sm[OFF_Z1 + r0] = z; sm[OFF_D1 + r0] = d;
                sp_sg(s1 + sm[OFF_BV1 + r1], z, d);
                sm[OFF_Z1 + r1] = z; sm[OFF_D1 + r1] = d;
            }
        }
        __syncthreads();

        // --- C: V slice = tanh(Wv2s z1 + bv2s); push to peers
        {
            const ulonglong2* z2 = (const ulonglong2*)&sm[OFF_Z1];
            u64t a0 = 0, a1 = 0;
            #pragma unroll
            for (int j = 0; j < 8; j++) {
                ulonglong2 zv = z2[kq * 8 + j];
                a0 = ffma2(w2[2 * j],     zv.x, a0);
                a0 = ffma2(w2[2 * j + 1], zv.y, a0);
                a1 = ffma2(w2[16 + 2 * j],     zv.x, a1);
                a1 = ffma2(w2[16 + 2 * j + 1], zv.y, a1);
            }
            float s0 = qsum(fold2(a0));
            float s1 = qsum(fold2(a1));
            if (kq == 0) {
                float v0 = tanh_ap(s0 + sm[OFF_BV2S + r0]);
                float v1 = tanh_ap(s1 + sm[OFF_BV2S + r1]);
                int vi0 = OFF_V + kH * rank + r0;
                int vi1 = vi0 + 1;
                sm[vi0] = v0; sm[vi1] = v1;
                sm[OFF_TDS + r0] = 1.f - v0 * v0;
                sm[OFF_TDS + r1] = 1.f - v1 * v1;
                peer[0][vi0] = v0; peer[0][vi1] = v1;
                peer[1][vi0] = v0; peer[1][vi1] = v1;
                peer[2][vi0] = v0; peer[2][vi1] = v1;
            }
        }
        cluster.sync();   // V(n) gathered everywhere

        // --- D: tangents w_dl = sum_e C[dl,e] V_e (own 2 channels)
        if (t < kH) {
            int dl = t >> 6, a_ = t & 63;
            const float* cj = &sm[OFF_CH + n * 16 + dl * 8];
            float acc = 0.f;
            #pragma unroll
            for (int e = 0; e < kD; e++)
                acc = fmaf(cj[e], sm[OFF_V + e * kS + a_], acc);
            sm[OFF_WT + dl * kS + a_] = acc;
        }
        __syncthreads();

        // --- E: pt_c = D0 .* (Wv0 wt_c), both channels
        //     WT: 2 x 64 floats -> ull2: ch0 at [0,16), ch1 at [16,32)
        {
            const ulonglong2* wt2 = (const ulonglong2*)&sm[OFF_WT];
            u64t a00 = 0, a01 = 0, a10 = 0, a11 = 0;
            #pragma unroll
            for (int j = 0; j < 4; j++) {
                ulonglong2 v0 = wt2[kq * 4 + j];
                ulonglong2 v1 = wt2[16 + kq * 4 + j];
                a00 = ffma2(w0[2 * j],     v0.x, a00);
                a00 = ffma2(w0[2 * j + 1], v0.y, a00);
                a01 = ffma2(w0[8 + 2 * j],     v0.x, a01);
                a01 = ffma2(w0[8 + 2 * j + 1], v0.y, a01);
                a10 = ffma2(w0[2 * j],     v1.x, a10);
                a10 = ffma2(w0[2 * j + 1], v1.y, a10);
                a11 = ffma2(w0[8 + 2 * j],     v1.x, a11);
                a11 = ffma2(w0[8 + 2 * j + 1], v1.y, a11);
            }
            float s00 = qsum(fold2(a00));   // (row r0, ch0)
            float s01 = qsum(fold2(a01));   // (row r1, ch0)
            float s10 = qsum(fold2(a10));   // (row r0, ch1)
            float s11 = qsum(fold2(a11));   // (row r1, ch1)
            if (kq == 0) {
                float d00 = sm[OFF_D0 + r0], d01 = sm[OFF_D0 + r1];
                sm[OFF_PT + r0]      = s00 * d00;
                sm[OFF_PT + r1]      = s01 * d01;
                sm[OFF_PT + kH + r0] = s10 * d00;
                sm[OFF_PT + kH + r1] = s11 * d01;
            }
        }
        __syncthreads();

        // --- F: ut_c = D1 .* (Wv1 pt_c), both channels
        //     PT: 2 x 128 floats -> ull2: ch0 at [0,32), ch1 at [32,64)
        {
            const ulonglong2* p2 = (const ulonglong2*)&sm[OFF_PT];
            u64t a00 = 0, a01 = 0, a10 = 0, a11 = 0;
            #pragma unroll
            for (int j = 0; j < 8; j++) {
                ulonglong2 v0 = p2[kq * 8 + j];
                ulonglong2 v1 = p2[32 + kq * 8 + j];
                a00 = ffma2(w1[2 * j],     v0.x, a00);
                a00 = ffma2(w1[2 * j + 1], v0.y, a00);
                a01 = ffma2(w1[16 + 2 * j],     v0.x, a01);
                a01 = ffma2(w1[16 + 2 * j + 1], v0.y, a01);
                a10 = ffma2(w1[2 * j],     v1.x, a10);
                a10 = ffma2(w1[2 * j + 1], v1.y, a10);
                a11 = ffma2(w1[16 + 2 * j],     v1.x, a11);
                a11 = ffma2(w1[16 + 2 * j + 1], v1.y, a11);
            }
            float s00 = qsum(fold2(a00));
            float s01 = qsum(fold2(a01));
            float s10 = qsum(fold2(a10));
            float s11 = qsum(fold2(a11));
            if (kq == 0) {
                float d10 = sm[OFF_D1 + r0], d11 = sm[OFF_D1 + r1];
                sm[OFF_UT + r0]      = s00 * d10;
                sm[OFF_UT + r1]      = s01 * d11;
                sm[OFF_UT + kH + r0] = s10 * d10;
                sm[OFF_UT + kH + r1] = s11 * d11;
            }
        }
        __syncthreads();

        // --- G: rd = TDS .* (Wv2s ut_{channel(row)})
        {
            int ch = rp >> 5;   // rows r0,r1 belong to channel ch
            const ulonglong2* u2 = (const ulonglong2*)&sm[OFF_UT + ch * kH];
            u64t a0 = 0, a1 = 0;
            #pragma unroll
            for (int j = 0; j < 8; j++) {
                ulonglong2 uv = u2[kq * 8 + j];
                a0 = ffma2(w2[2 * j],     uv.x, a0);
                a0 = ffma2(w2[2 * j + 1], uv.y, a0);
                a1 = ffma2(w2[16 + 2 * j],     uv.x, a1);
                a1 = ffma2(w2[16 + 2 * j + 1], uv.y, a1);
            }
            float s0 = qsum(fold2(a0));
            float s1 = qsum(fold2(a1));
            if (kq == 0) {
                sm[OFF_RD + r0] = s0 * sm[OFF_TDS + r0];
                sm[OFF_RD + r1] = s1 * sm[OFF_TDS + r1];
            }
        }
        __syncthreads();

        // --- fold: correction c = rd folded + a.V(own channels); push
        if (t < kS) {
            const float* sgn = &sm[OFF_SIGS + n * 36];
            float rs = sm[OFF_RD + t] + sm[OFF_RD + kS + t]
                     + sgn[d0g]     * sm[OFF_V + d0g * kS + t]
                     + sgn[d0g + 1] * sm[OFF_V + (d0g + 1) * kS + t];
            int ri = OFF_RSLOT + kS * rank + t;
            sm[ri] = rs;
            peer[0][ri] = rs;
            peer[1][ri] = rs;
            peer[2][ri] = rs;
        }
        cluster.sync();   // corrections gathered everywhere

        // --- H: h_{n+1} = h_n + sum_p c_p
        if (t < kS) {
            float acc = sm[OFF_HH + n * kS + t];
            #pragma unroll
            for (int p = 0; p < CL; p++)
                acc += sm[OFF_RSLOT + p * kS + t];
            sm[OFF_HH + (n + 1) * kS + t] = acc;
        }
        __syncthreads();
    }

    // ---- readout of the full h history (rank 0, parallel GEMM) ----
    if (rank == 0) {
        for (int idx = t; idx < (kNW + 1) * kOut; idx += NT) {
            int n = idx >> 3, oo = idx & 7;
            float acc = sm[OFF_BR + oo];
            const float* hh = &sm[OFF_HH + n * kS];
            #pragma unroll 16
            for (int a = 0; a < kS; a++)
                acc = fmaf(sm[OFF_WR + oo * kS + a], hh[a], acc);
            out[((size_t)b * (kNW + 1) + n) * kOut + oo] = acc;
        }
    }
    cluster.sync();   // no CTA exits while peers may still touch its smem
}

extern "C" void kernel_launch(void* const* d_in, const int* in_sizes, int n_in,
                              void* d_out, int out_size) {
    // metadata order: ts, x, Wi0,bi0, Wi1,bi1, Wi2,bi2, Wv0,bv0, Wv1,bv1, Wv2,bv2, Wr,br
    const float* x   = (const float*)d_in[1];
    const float* Wi0 = (const float*)d_in[2];
    const float* bi0 = (const float*)d_in[3];
    const float* Wi1 = (const float*)d_in[4];
    const float* bi1 = (const float*)d_in[5];
    const float* Wi2 = (const float*)d_in[6];
    const float* bi2 = (const float*)d_in[7];
    const float* Wv0 = (const float*)d_in[8];
    const float* bv0 = (const float*)d_in[9];
    const float* Wv1 = (const float*)d_in[10];
    const float* bv1 = (const float*)d_in[11];
    const float* Wv2 = (const float*)d_in[12];
    const float* bv2 = (const float*)d_in[13];
    const float* Wr  = (const float*)d_in[14];
    const float* br  = (const float*)d_in[15];
    float* out = (float*)d_out;

    logncde_prep_kernel<<<kB, 128>>>(x, Wi0, bi0, Wi1, bi1, Wi2, bi2);

    cudaFuncSetAttribute(logncde_v12_kernel,
                         cudaFuncAttributeMaxDynamicSharedMemorySize,
                         SMEMF * (int)sizeof(float));
    logncde_v12_kernel<<<kB * CL, NT, SMEMF * sizeof(float)>>>(
        Wv0, bv0, Wv1, bv1, Wv2, bv2, Wr, br, out);
}

// round 13
// speedup vs baseline: 1.1773x; 1.1773x over previous
#include <cuda_runtime.h>
#include <cooperative_groups.h>
#include <math.h>
#include <stdint.h>

namespace cg = cooperative_groups;

// ---------------------------------------------------------------------------
// LogNCDE depth-2 log-ODE scan, 4-CTA cluster per batch element (128 CTAs).
// Rank r owns channels {2r,2r+1} and Wv2 rows [128r,128r+128).
// v13: thread t owns 4 rows (og=t>>3, rows 4og..4og+3) x k-eighth (kq=t&7).
// All 8 k-partials of an output sit in one lane-octet -> 3 shfl_xor, kq==0
// lane applies activation and does one float4 store. Same activation
// bytes/MAC as v6 but no smem partial trees: 7 barriers + 2 cluster.syncs.
// Weights in registers (160 regs, f32x2). Prep kernel computes sigs + h0.
// ---------------------------------------------------------------------------

namespace {
constexpr int kB   = 32;
constexpr int kT   = 2049;
constexpr int kD   = 8;
constexpr int kS   = 64;
constexpr int kH   = 128;
constexpr int kP   = 28;
constexpr int kNW  = 128;
constexpr int kWin = 16;
constexpr int kOut = 8;
constexpr int CL   = 4;
constexpr int NT   = 256;

// shared-memory float offsets (16B aligned)
constexpr int OFF_SIGS  = 0;        // [128][36]
constexpr int OFF_CH    = 4608;     // [128][16]
constexpr int OFF_BV0   = 6656;     // 128
constexpr int OFF_BV1   = 6784;     // 128
constexpr int OFF_BV2S  = 6912;     // 128
constexpr int OFF_WR    = 7040;     // 512
constexpr int OFF_BR    = 7552;     // 16
constexpr int OFF_HH    = 7568;     // [129][64]
constexpr int OFF_Z0    = 15824;    // 128
constexpr int OFF_D0    = 15952;    // 128
constexpr int OFF_Z1    = 16080;    // 128
constexpr int OFF_D1    = 16208;    // 128
constexpr int OFF_V     = 16336;    // 512 (single buffer)
constexpr int OFF_TDS   = 16848;    // 128
constexpr int OFF_WT    = 16976;    // 2 x 64
constexpr int OFF_PT    = 17104;    // 2 x 128
constexpr int OFF_UT    = 17360;    // 2 x 128
constexpr int OFF_RD    = 17616;    // 128
constexpr int OFF_RSLOT = 17744;    // 4 x 64
constexpr int SMEMF     = 18000;    // 72 KB
}  // namespace

__device__ float g_sigs[kB * kNW * 36];   // per-batch window signatures
__device__ float g_h0[kB * kS];           // per-batch initial state

static __device__ const int c_II[kP] =
    {0,0,0,0,0,0,0,1,1,1,1,1,1,2,2,2,2,2,3,3,3,3,4,4,4,5,5,6};
static __device__ const int c_JJ[kP] =
    {1,2,3,4,5,6,7,2,3,4,5,6,7,3,4,5,6,7,4,5,6,7,5,6,7,6,7,7};

using u64t = unsigned long long;

__device__ __forceinline__ int pidx(int i, int j) {   // Lyndon pair index, i<j
    return 7 * i - (i * (i - 1)) / 2 + (j - i - 1);
}
__device__ __forceinline__ u64t ffma2(u64t a, u64t b, u64t c) {
    u64t r;
    asm("fma.rn.f32x2 %0, %1, %2, %3;" : "=l"(r) : "l"(a), "l"(b), "l"(c));
    return r;
}
__device__ __forceinline__ float fold2(u64t a) {
    float lo, hi;
    asm("mov.b64 {%0, %1}, %2;" : "=f"(lo), "=f"(hi) : "l"(a));
    return lo + hi;
}
__device__ __forceinline__ float osum(float s) {   // octet reduce (kq lanes)
    s += __shfl_xor_sync(0xffffffffu, s, 1);
    s += __shfl_xor_sync(0xffffffffu, s, 2);
    s += __shfl_xor_sync(0xffffffffu, s, 4);
    return s;
}
__device__ __forceinline__ float tanh_ap(float x) {
    float r; asm("tanh.approx.f32 %0, %1;" : "=f"(r) : "f"(x)); return r;
}
__device__ __forceinline__ void sp_sg(float s, float& z, float& d) {
    if (s > 20.f) { z = s; d = 1.f; }
    else {
        float e = __expf(s);
        float inv = __frcp_rn(1.f + e);
        z = __logf(1.f + e);
        d = e * inv;
    }
}
__device__ __forceinline__ float sp_f(float x) {   // accurate (one-time h0)
    return (x > 20.f) ? x : log1pf(expf(x));
}

// ======================= prep kernel: signatures + h0 =======================
__global__ __launch_bounds__(128, 1)
void logncde_prep_kernel(
    const float* __restrict__ x,
    const float* __restrict__ Wi0, const float* __restrict__ bi0,
    const float* __restrict__ Wi1, const float* __restrict__ bi1,
    const float* __restrict__ Wi2, const float* __restrict__ bi2)
{
    __shared__ float z0[kH], z1[kH];
    const int b = blockIdx.x;
    const int t = threadIdx.x;

    // depth-2 log-signature, one window per thread
    {
        const float* xb = x + (size_t)b * kT * kD + (size_t)t * kWin * kD;
        float cum[kD], prev[kD], Mm[kD * kD];
        #pragma unroll
        for (int i = 0; i < kD; i++) { cum[i] = 0.f; prev[i] = xb[i]; }
        #pragma unroll
        for (int i = 0; i < kD * kD; i++) Mm[i] = 0.f;
        for (int w = 0; w < kWin; w++) {
            float dl[kD];
            #pragma unroll
            for (int j = 0; j < kD; j++) {
                float c = xb[(w + 1) * kD + j];
                dl[j] = c - prev[j];
                prev[j] = c;
            }
            #pragma unroll
            for (int i = 0; i < kD; i++)
                #pragma unroll
                for (int j = 0; j < kD; j++)
                    Mm[i * kD + j] = fmaf(cum[i], dl[j], Mm[i * kD + j]);
            #pragma unroll
            for (int i = 0; i < kD; i++) cum[i] += dl[i];
        }
        float* sgw = &g_sigs[((size_t)b * kNW + t) * 36];
        #pragma unroll
        for (int i = 0; i < kD; i++) sgw[i] = cum[i];
        #pragma unroll
        for (int p = 0; p < kP; p++) {
            int i = c_II[p], j = c_JJ[p];
            sgw[8 + p] = 0.5f * (Mm[i * kD + j] - Mm[j * kD + i]);
        }
    }

    // initial MLP h0 (accurate path)
    const float* x0 = x + (size_t)b * kT * kD;
    {
        float acc = bi0[t];
        #pragma unroll
        for (int k = 0; k < kD; k++) acc = fmaf(Wi0[t * kD + k], x0[k], acc);
        z0[t] = sp_f(acc);
    }
    __syncthreads();
    {
        float acc = bi1[t];
        #pragma unroll 16
        for (int k = 0; k < kH; k++) acc = fmaf(Wi1[t * kH + k], z0[k], acc);
        z1[t] = sp_f(acc);
    }
    __syncthreads();
    if (t < kS) {
        float acc = bi2[t];
        #pragma unroll 16
        for (int k = 0; k < kH; k++) acc = fmaf(Wi2[t * kH + k], z1[k], acc);
        g_h0[b * kS + t] = acc;
    }
}

// ============================== scan kernel ================================
__global__ __launch_bounds__(NT, 1) __cluster_dims__(CL, 1, 1)
void logncde_v13_kernel(
    const float* __restrict__ Wv0, const float* __restrict__ bv0,
    const float* __restrict__ Wv1, const float* __restrict__ bv1,
    const float* __restrict__ Wv2, const float* __restrict__ bv2,
    const float* __restrict__ Wr,  const float* __restrict__ br,
    float* __restrict__ out)
{
    extern __shared__ float sm[];
    cg::cluster_group cluster = cg::this_cluster();
    const int t    = threadIdx.x;
    const int rank = (int)cluster.block_rank();
    const int b    = blockIdx.x >> 2;
    const int d0g  = 2 * rank;
    const int og   = t >> 3;     // row group 0..31 (rows 4og..4og+3)
    const int kq   = t & 7;      // k-eighth
    const int row0 = 4 * og;

    float* peer[CL - 1];
    #pragma unroll
    for (int p = 1; p < CL; p++)
        peer[p - 1] = cluster.map_shared_rank(sm, (rank + p) & (CL - 1));

    // ---- register weight tiles: 4 rows x k-eighth, packed f32x2 ----
    // Wv0 row = 16 ull2; eighth = 2 ull2 -> w0[16] u64 (4 u64/row)
    // Wv1/Wv2 row = 32 ull2; eighth = 4 ull2 -> 32 u64 (8 u64/row)
    u64t w0[16], w1[32], w2[32];
    {
        const ulonglong2* W0 = (const ulonglong2*)Wv0;
        #pragma unroll
        for (int rr = 0; rr < 4; rr++)
            #pragma unroll
            for (int j = 0; j < 2; j++) {
                ulonglong2 v = W0[(row0 + rr) * 16 + kq * 2 + j];
                w0[rr * 4 + 2 * j]     = v.x;
                w0[rr * 4 + 2 * j + 1] = v.y;
            }
        const ulonglong2* W1 = (const ulonglong2*)Wv1;
        #pragma unroll
        for (int rr = 0; rr < 4; rr++)
            #pragma unroll
            for (int j = 0; j < 4; j++) {
                ulonglong2 v = W1[(row0 + rr) * 32 + kq * 4 + j];
                w1[rr * 8 + 2 * j]     = v.x;
                w1[rr * 8 + 2 * j + 1] = v.y;
            }
        const ulonglong2* W2 = (const ulonglong2*)Wv2;
        #pragma unroll
        for (int rr = 0; rr < 4; rr++)
            #pragma unroll
            for (int j = 0; j < 4; j++) {
                ulonglong2 v = W2[(kH * rank + row0 + rr) * 32 + kq * 4 + j];
                w2[rr * 8 + 2 * j]     = v.x;
                w2[rr * 8 + 2 * j + 1] = v.y;
            }
    }

    // ---- staging ----
    for (int i = t; i < kH; i += NT) {
        sm[OFF_BV0 + i]  = bv0[i];
        sm[OFF_BV1 + i]  = bv1[i];
        sm[OFF_BV2S + i] = bv2[kH * rank + i];
    }
    for (int i = t; i < kOut * kS; i += NT) sm[OFF_WR + i] = Wr[i];
    if (t < kOut) sm[OFF_BR + t] = br[t];
    {
        const float* src = &g_sigs[(size_t)b * kNW * 36];
        for (int i = t; i < kNW * 36; i += NT) sm[OFF_SIGS + i] = src[i];
    }
    if (t < kS) sm[OFF_HH + t] = g_h0[b * kS + t];
    __syncthreads();

    // ---- precompute C coefficients for all steps (this rank's channels) ----
    for (int i = t; i < kNW * 16; i += NT) {
        int n = i >> 4, j = i & 15;
        int dl = j >> 3, e = j & 7;
        int d = d0g + dl;
        const float* sgn = &sm[OFF_SIGS + n * 36];
        float v = 0.f;
        if (e < d)      v =  sgn[8 + pidx(e, d)];
        else if (e > d) v = -sgn[8 + pidx(d, e)];
        sm[OFF_CH + n * 16 + dl * 8 + e] = v;
    }

    cluster.sync();

    // ============================ scan loop ============================
    for (int n = 0; n < kNW; n++) {

        // --- A: z0 = sp(Wv0 h + bv0)
        {
            const ulonglong2* h2 = (const ulonglong2*)&sm[OFF_HH + n * kS];
            u64t a0 = 0, a1 = 0, a2 = 0, a3 = 0;
            #pragma unroll
            for (int j = 0; j < 2; j++) {
                ulonglong2 hv = h2[kq * 2 + j];
                a0 = ffma2(w0[0 * 4 + 2 * j], hv.x, a0);
                a0 = ffma2(w0[0 * 4 + 2 * j + 1], hv.y, a0);
                a1 = ffma2(w0[1 * 4 + 2 * j], hv.x, a1);
                a1 = ffma2(w0[1 * 4 + 2 * j + 1], hv.y, a1);
                a2 = ffma2(w0[2 * 4 + 2 * j], hv.x, a2);
                a2 = ffma2(w0[2 * 4 + 2 * j + 1], hv.y, a2);
                a3 = ffma2(w0[3 * 4 + 2 * j], hv.x, a3);
                a3 = ffma2(w0[3 * 4 + 2 * j + 1], hv.y, a3);
            }
            float s0 = osum(fold2(a0));
            float s1 = osum(fold2(a1));
            float s2 = osum(fold2(a2));
            float s3 = osum(fold2(a3));
            if (kq == 0) {
                const float4 bz = *(const float4*)&sm[OFF_BV0 + row0];
                float4 z, d;
                sp_sg(s0 + bz.x, z.x, d.x);
                sp_sg(s1 + bz.y, z.y, d.y);
                sp_sg(s2 + bz.z, z.z, d.z);
                sp_sg(s3 + bz.w, z.w, d.w);
                *(float4*)&sm[OFF_Z0 + row0] = z;
                *(float4*)&sm[OFF_D0 + row0] = d;
            }
        }
        __syncthreads();

        // --- B: z1 = sp(Wv1 z0 + bv1)
        {
            const ulonglong2* z2 = (const ulonglong2*)&sm[OFF_Z0];
            u64t a0 = 0, a1 = 0, a2 = 0, a3 = 0;
            #pragma unroll
            for (int j = 0; j < 4; j++) {
                ulonglong2 zv = z2[kq * 4 + j];
                a0 = ffma2(w1[0 * 8 + 2 * j], zv.x, a0);
                a0 = ffma2(w1[0 * 8 + 2 * j + 1], zv.y, a0);
                a1 = ffma2(w1[1 * 8 + 2 * j], zv.x, a1);
                a1 = ffma2(w1[1 * 8 + 2 * j + 1], zv.y, a1);
                a2 = ffma2(w1[2 * 8 + 2 * j], zv.x, a2);
                a2 = ffma2(w1[2 * 8 + 2 * j + 1], zv.y, a2);
                a3 = ffma2(w1[3 * 8 + 2 * j], zv.x, a3);
                a3 = ffma2(w1[3 * 8 + 2 * j + 1], zv.y, a3);
            }
            float s0 = osum(fold2(a0));
            float s1 = osum(fold2(a1));
            float s2 = osum(fold2(a2));
            float s3 = osum(fold2(a3));
            if (kq == 0) {
                const float4 bz = *(const float4*)&sm[OFF_BV1 + row0];
                float4 z, d;
                sp_sg(s0 + bz.x, z.x, d.x);
                sp_sg(s1 + bz.y, z.y, d.y);
                sp_sg(s2 + bz.z, z.z, d.z);
                sp_sg(s3 + bz.w, z.w, d.w);
                *(float4*)&sm[OFF_Z1 + row0] = z;
                *(float4*)&sm[OFF_D1 + row0] = d;
            }
        }
        __syncthreads();

        // --- C: V slice = tanh(Wv2s z1 + bv2s); push slice to peers
        {
            const ulonglong2* z2 = (const ulonglong2*)&sm[OFF_Z1];
            u64t a0 = 0, a1 = 0, a2 = 0, a3 = 0;
            #pragma unroll
            for (int j = 0; j < 4; j++) {
                ulonglong2 zv = z2[kq * 4 + j];
                a0 = ffma2(w2[0 * 8 + 2 * j], zv.x, a0);
                a0 = ffma2(w2[0 * 8 + 2 * j + 1], zv.y, a0);
                a1 = ffma2(w2[1 * 8 + 2 * j], zv.x, a1);
                a1 = ffma2(w2[1 * 8 + 2 * j + 1], zv.y, a1);
                a2 = ffma2(w2[2 * 8 + 2 * j], zv.x, a2);
                a2 = ffma2(w2[2 * 8 + 2 * j + 1], zv.y, a2);
                a3 = ffma2(w2[3 * 8 + 2 * j], zv.x, a3);
                a3 = ffma2(w2[3 * 8 + 2 * j + 1], zv.y, a3);
            }
            float s0 = osum(fold2(a0));
            float s1 = osum(fold2(a1));
            float s2 = osum(fold2(a2));
            float s3 = osum(fold2(a3));
            if (kq == 0) {
                const float4 bz = *(const float4*)&sm[OFF_BV2S + row0];
                float4 v, td;
                v.x = tanh_ap(s0 + bz.x);
                v.y = tanh_ap(s1 + bz.y);
                v.z = tanh_ap(s2 + bz.z);
                v.w = tanh_ap(s3 + bz.w);
                td.x = 1.f - v.x * v.x;
                td.y = 1.f - v.y * v.y;
                td.z = 1.f - v.z * v.z;
                td.w = 1.f - v.w * v.w;
                int vi = OFF_V + kH * rank + row0;
                *(float4*)&sm[vi] = v;
                *(float4*)&sm[OFF_TDS + row0] = td;
                *(float4*)&peer[0][vi] = v;
                *(float4*)&peer[1][vi] = v;
                *(float4*)&peer[2][vi] = v;
            }
        }
        cluster.sync();   // V(n) gathered everywhere

        // --- D: tangents w_dl = sum_e C[dl,e] V_e (own 2 channels)
        if (t < kH) {
            int dl = t >> 6, a_ = t & 63;
            const float* cj = &sm[OFF_CH + n * 16 + dl * 8];
            float acc = 0.f;
            #pragma unroll
            for (int e = 0; e < kD; e++)
                acc = fmaf(cj[e], sm[OFF_V + e * kS + a_], acc);
            sm[OFF_WT + dl * kS + a_] = acc;
        }
        __syncthreads();

        // --- E: pt_c = D0 .* (Wv0 wt_c), both channels
        //     WT ull2: ch0 at [0,16), ch1 at [16,32)
        {
            const ulonglong2* wt2 = (const ulonglong2*)&sm[OFF_WT];
            u64t a0 = 0, a1 = 0, a2 = 0, a3 = 0;   // channel 0, rows 0..3
            u64t b0 = 0, b1 = 0, b2 = 0, b3 = 0;   // channel 1
            #pragma unroll
            for (int j = 0; j < 2; j++) {
                ulonglong2 v0 = wt2[kq * 2 + j];
                ulonglong2 v1 = wt2[16 + kq * 2 + j];
                a0 = ffma2(w0[0 * 4 + 2 * j], v0.x, a0);
                a0 = ffma2(w0[0 * 4 + 2 * j + 1], v0.y, a0);
                a1 = ffma2(w0[1 * 4 + 2 * j], v0.x, a1);
                a1 = ffma2(w0[1 * 4 + 2 * j + 1], v0.y, a1);
                a2 = ffma2(w0[2 * 4 + 2 * j], v0.x, a2);
                a2 = ffma2(w0[2 * 4 + 2 * j + 1], v0.y, a2);
                a3 = ffma2(w0[3 * 4 + 2 * j], v0.x, a3);
                a3 = ffma2(w0[3 * 4 + 2 * j + 1], v0.y, a3);
                b0 = ffma2(w0[0 * 4 + 2 * j], v1.x, b0);
                b0 = ffma2(w0[0 * 4 + 2 * j + 1], v1.y, b0);
                b1 = ffma2(w0[1 * 4 + 2 * j], v1.x, b1);
                b1 = ffma2(w0[1 * 4 + 2 * j + 1], v1.y, b1);
                b2 = ffma2(w0[2 * 4 + 2 * j], v1.x, b2);
                b2 = ffma2(w0[2 * 4 + 2 * j + 1], v1.y, b2);
                b3 = ffma2(w0[3 * 4 + 2 * j], v1.x, b3);
                b3 = ffma2(w0[3 * 4 + 2 * j + 1], v1.y, b3);
            }
            float s0 = osum(fold2(a0));
            float s1 = osum(fold2(a1));
            float s2 = osum(fold2(a2));
            float s3 = osum(fold2(a3));
            float u0 = osum(fold2(b0));
            float u1 = osum(fold2(b1));
            float u2 = osum(fold2(b2));
            float u3 = osum(fold2(b3));
            if (kq == 0) {
                const float4 dv = *(const float4*)&sm[OFF_D0 + row0];
                float4 p0 = make_float4(s0 * dv.x, s1 * dv.y, s2 * dv.z, s3 * dv.w);
                float4 p1 = make_float4(u0 * dv.x, u1 * dv.y, u2 * dv.z, u3 * dv.w);
                *(float4*)&sm[OFF_PT + row0]      = p0;
                *(float4*)&sm[OFF_PT + kH + row0] = p1;
            }
        }
        __syncthreads();

        // --- F: ut_c = D1 .* (Wv1 pt_c), both channels
        //     PT ull2: ch0 at [0,32), ch1 at [32,64)
        {
            const ulonglong2* p2 = (const ulonglong2*)&sm[OFF_PT];
            u64t a0 = 0, a1 = 0, a2 = 0, a3 = 0;
            u64t b0 = 0, b1 = 0, b2 = 0, b3 = 0;
            #pragma unroll
            for (int j = 0; j < 4; j++) {
                ulonglong2 v0 = p2[kq * 4 + j];
                ulonglong2 v1 = p2[32 + kq * 4 + j];
                a0 = ffma2(w1[0 * 8 + 2 * j], v0.x, a0);
                a0 = ffma2(w1[0 * 8 + 2 * j + 1], v0.y, a0);
                a1 = ffma2(w1[1 * 8 + 2 * j], v0.x, a1);
                a1 = ffma2(w1[1 * 8 + 2 * j + 1], v0.y, a1);
                a2 = ffma2(w1[2 * 8 + 2 * j], v0.x, a2);
                a2 = ffma2(w1[2 * 8 + 2 * j + 1], v0.y, a2);
                a3 = ffma2(w1[3 * 8 + 2 * j], v0.x, a3);
                a3 = ffma2(w1[3 * 8 + 2 * j + 1], v0.y, a3);
                b0 = ffma2(w1[0 * 8 + 2 * j], v1.x, b0);
                b0 = ffma2(w1[0 * 8 + 2 * j + 1], v1.y, b0);
                b1 = ffma2(w1[1 * 8 + 2 * j], v1.x, b1);
                b1 = ffma2(w1[1 * 8 + 2 * j + 1], v1.y, b1);
                b2 = ffma2(w1[2 * 8 + 2 * j], v1.x, b2);
                b2 = ffma2(w1[2 * 8 + 2 * j + 1], v1.y, b2);
                b3 = ffma2(w1[3 * 8 + 2 * j], v1.x, b3);
                b3 = ffma2(w1[3 * 8 + 2 * j + 1], v1.y, b3);
            }
            float s0 = osum(fold2(a0));
            float s1 = osum(fold2(a1));
            float s2 = osum(fold2(a2));
            float s3 = osum(fold2(a3));
            float u0 = osum(fold2(b0));
            float u1 = osum(fold2(b1));
            float u2 = osum(fold2(b2));
            float u3 = osum(fold2(b3));
            if (kq == 0) {
                const float4 dv = *(const float4*)&sm[OFF_D1 + row0];
                float4 p0 = make_float4(s0 * dv.x, s1 * dv.y, s2 * dv.z, s3 * dv.w);
                float4 p1 = make_float4(u0 * dv.x, u1 * dv.y, u2 * dv.z, u3 * dv.w);
                *(float4*)&sm[OFF_UT + row0]      = p0;
                *(float4*)&sm[OFF_UT + kH + row0] = p1;
            }
        }
        __syncthreads();

        // --- G: rd = TDS .* (Wv2s ut_{channel(row)})
        {
            int ch = og >> 4;   // rows 4og..4og+3 belong to channel ch
            const ulonglong2* u2v = (const ulonglong2*)&sm[OFF_UT + ch * kH];
            u64t a0 = 0, a1 = 0, a2 = 0, a3 = 0;
            #pragma unroll
            for (int j = 0; j < 4; j++) {
                ulonglong2 uv = u2v[kq * 4 + j];
                a0 = ffma2(w2[0 * 8 + 2 * j], uv.x, a0);
                a0 = ffma2(w2[0 * 8 + 2 * j + 1], uv.y, a0);
                a1 = ffma2(w2[1 * 8 + 2 * j], uv.x, a1);
                a1 = ffma2(w2[1 * 8 + 2 * j + 1], uv.y, a1);
                a2 = ffma2(w2[2 * 8 + 2 * j], uv.x, a2);
                a2 = ffma2(w2[2 * 8 + 2 * j + 1], uv.y, a2);
                a3 = ffma2(w2[3 * 8 + 2 * j], uv.x, a3);
                a3 = ffma2(w2[3 * 8 + 2 * j + 1], uv.y, a3);
            }
            float s0 = osum(fold2(a0));
            float s1 = osum(fold2(a1));
            float s2 = osum(fold2(a2));
            float s3 = osum(fold2(a3));
            if (kq == 0) {
                const float4 td = *(const float4*)&sm[OFF_TDS + row0];
                float4 rdv = make_float4(s0 * td.x, s1 * td.y, s2 * td.z, s3 * td.w);
                *(float4*)&sm[OFF_RD + row0] = rdv;
            }
        }
        __syncthreads();

        // --- fold: correction c = rd folded + a.V(own channels); push
        if (t < kS) {
            const float* sgn = &sm[OFF_SIGS + n * 36];
            float rs = sm[OFF_RD + t] + sm[OFF_RD + kS + t]
                     + sgn[d0g]     * sm[OFF_V + d0g * kS + t]
                     + sgn[d0g + 1] * sm[OFF_V + (d0g + 1) * kS + t];
            int ri = OFF_RSLOT + kS * rank + t;
            sm[ri] = rs;
            peer[0][ri] = rs;
            peer[1][ri] = rs;
            peer[2][ri] = rs;
        }
        cluster.sync();   // corrections gathered everywhere

        // --- H: h_{n+1} = h_n + sum_p c_p
        if (t < kS) {
            float acc = sm[OFF_HH + n * kS + t];
            #pragma unroll
            for (int p = 0; p < CL; p++)
                acc += sm[OFF_RSLOT + p * kS + t];
            sm[OFF_HH + (n + 1) * kS + t] = acc;
        }
        __syncthreads();
    }

    // ---- readout of the full h history (rank 0, parallel GEMM) ----
    if (rank == 0) {
        for (int idx = t; idx < (kNW + 1) * kOut; idx += NT) {
            int n = idx >> 3, oo = idx & 7;
            float acc = sm[OFF_BR + oo];
            const float* hh = &sm[OFF_HH + n * kS];
            #pragma unroll 16
            for (int a = 0; a < kS; a++)
                acc = fmaf(sm[OFF_WR + oo * kS + a], hh[a], acc);
            out[((size_t)b * (kNW + 1) + n) * kOut + oo] = acc;
        }
    }
    cluster.sync();   // no CTA exits while peers may still touch its smem
}

extern "C" void kernel_launch(void* const* d_in, const int* in_sizes, int n_in,
                              void* d_out, int out_size) {
    // metadata order: ts, x, Wi0,bi0, Wi1,bi1, Wi2,bi2, Wv0,bv0, Wv1,bv1, Wv2,bv2, Wr,br
    const float* x   = (const float*)d_in[1];
    const float* Wi0 = (const float*)d_in[2];
    const float* bi0 = (const float*)d_in[3];
    const float* Wi1 = (const float*)d_in[4];
    const float* bi1 = (const float*)d_in[5];
    const float* Wi2 = (const float*)d_in[6];
    const float* bi2 = (const float*)d_in[7];
    const float* Wv0 = (const float*)d_in[8];
    const float* bv0 = (const float*)d_in[9];
    const float* Wv1 = (const float*)d_in[10];
    const float* bv1 = (const float*)d_in[11];
    const float* Wv2 = (const float*)d_in[12];
    const float* bv2 = (const float*)d_in[13];
    const float* Wr  = (const float*)d_in[14];
    const float* br  = (const float*)d_in[15];
    float* out = (float*)d_out;

    logncde_prep_kernel<<<kB, 128>>>(x, Wi0, bi0, Wi1, bi1, Wi2, bi2);

    cudaFuncSetAttribute(logncde_v13_kernel,
                         cudaFuncAttributeMaxDynamicSharedMemorySize,
                         SMEMF * (int)sizeof(float));
    logncde_v13_kernel<<<kB * CL, NT, SMEMF * sizeof(float)>>>(
        Wv0, bv0, Wv1, bv1, Wv2, bv2, Wr, br, out);
}

// round 14
// speedup vs baseline: 2.0963x; 1.7807x over previous
#include <cuda_runtime.h>
#include <cooperative_groups.h>
#include <math.h>
#include <stdint.h>

namespace cg = cooperative_groups;

// ---------------------------------------------------------------------------
// LogNCDE depth-2 log-ODE scan, 4-CTA cluster per batch element (128 CTAs).
// Rank r owns channels {2r,2r+1} and Wv2 rows [128r,128r+128).
// v14 = v6 engine (register weight tiles 4 rows x k-octant, float4 smem
// partial trees, cluster.sync exchanges, precomputed C, fast activations,
// hoisted readout) + prep-kernel offload of sigs/h0 + a.V folded into the
// exchanged correction (single-buffered V).
// ---------------------------------------------------------------------------

namespace {
constexpr int kB   = 32;
constexpr int kT   = 2049;
constexpr int kD   = 8;
constexpr int kS   = 64;
constexpr int kH   = 128;
constexpr int kP   = 28;
constexpr int kNW  = 128;
constexpr int kWin = 16;
constexpr int kOut = 8;
constexpr int CL   = 4;
constexpr int NT   = 256;

// shared-memory float offsets (16B aligned)
constexpr int OFF_SIGS  = 0;        // [128][36]
constexpr int OFF_CH    = 4608;     // [128][16]
constexpr int OFF_BV0   = 6656;     // 128
constexpr int OFF_BV1   = 6784;     // 128
constexpr int OFF_BV2S  = 6912;     // 128
constexpr int OFF_WR    = 7040;     // 512
constexpr int OFF_BR    = 7552;     // 16
constexpr int OFF_HH    = 7568;     // [129][64]
constexpr int OFF_Z0    = 15824;    // 128
constexpr int OFF_D0    = 15952;    // 128
constexpr int OFF_Z1    = 16080;    // 128
constexpr int OFF_D1    = 16208;    // 128
constexpr int OFF_V     = 16336;    // 512 (single buffer)
constexpr int OFF_TDS   = 16848;    // 128
constexpr int OFF_WT    = 16976;    // 2 x 64
constexpr int OFF_PT    = 17104;    // 2 x 128
constexpr int OFF_UT    = 17360;    // 2 x 128
constexpr int OFF_RSLOT = 17616;    // 4 x 64
constexpr int OFF_PART  = 17872;    // 2 x 8 x 128 partials
constexpr int SMEMF     = 19920;    // ~80 KB
}  // namespace

__device__ float g_sigs[kB * kNW * 36];   // per-batch window signatures
__device__ float g_h0[kB * kS];           // per-batch initial state

static __device__ const int c_II[kP] =
    {0,0,0,0,0,0,0,1,1,1,1,1,1,2,2,2,2,2,3,3,3,3,4,4,4,5,5,6};
static __device__ const int c_JJ[kP] =
    {1,2,3,4,5,6,7,2,3,4,5,6,7,3,4,5,6,7,4,5,6,7,5,6,7,6,7,7};

__device__ __forceinline__ int pidx(int i, int j) {   // Lyndon pair index, i<j
    return 7 * i - (i * (i - 1)) / 2 + (j - i - 1);
}
__device__ __forceinline__ float dot4(float4 w, float4 v, float acc) {
    acc = fmaf(w.x, v.x, acc); acc = fmaf(w.y, v.y, acc);
    acc = fmaf(w.z, v.z, acc); acc = fmaf(w.w, v.w, acc);
    return acc;
}
__device__ __forceinline__ float tanh_ap(float x) {
    float r; asm("tanh.approx.f32 %0, %1;" : "=f"(r) : "f"(x)); return r;
}
__device__ __forceinline__ void sp_sg(float s, float& z, float& d) {
    if (s > 20.f) { z = s; d = 1.f; }
    else {
        float e = __expf(s);
        float inv = __frcp_rn(1.f + e);
        z = __logf(1.f + e);
        d = e * inv;
    }
}
__device__ __forceinline__ float sp_f(float x) {   // accurate (one-time h0)
    return (x > 20.f) ? x : log1pf(expf(x));
}

// ======================= prep kernel: signatures + h0 =======================
__global__ __launch_bounds__(128, 1)
void logncde_prep_kernel(
    const float* __restrict__ x,
    const float* __restrict__ Wi0, const float* __restrict__ bi0,
    const float* __restrict__ Wi1, const float* __restrict__ bi1,
    const float* __restrict__ Wi2, const float* __restrict__ bi2)
{
    __shared__ float z0[kH], z1[kH];
    const int b = blockIdx.x;
    const int t = threadIdx.x;

    // depth-2 log-signature, one window per thread
    {
        const float* xb = x + (size_t)b * kT * kD + (size_t)t * kWin * kD;
        float cum[kD], prev[kD], Mm[kD * kD];
        #pragma unroll
        for (int i = 0; i < kD; i++) { cum[i] = 0.f; prev[i] = xb[i]; }
        #pragma unroll
        for (int i = 0; i < kD * kD; i++) Mm[i] = 0.f;
        for (int w = 0; w < kWin; w++) {
            float dl[kD];
            #pragma unroll
            for (int j = 0; j < kD; j++) {
                float c = xb[(w + 1) * kD + j];
                dl[j] = c - prev[j];
                prev[j] = c;
            }
            #pragma unroll
            for (int i = 0; i < kD; i++)
                #pragma unroll
                for (int j = 0; j < kD; j++)
                    Mm[i * kD + j] = fmaf(cum[i], dl[j], Mm[i * kD + j]);
            #pragma unroll
            for (int i = 0; i < kD; i++) cum[i] += dl[i];
        }
        float* sgw = &g_sigs[((size_t)b * kNW + t) * 36];
        #pragma unroll
        for (int i = 0; i < kD; i++) sgw[i] = cum[i];
        #pragma unroll
        for (int p = 0; p < kP; p++) {
            int i = c_II[p], j = c_JJ[p];
            sgw[8 + p] = 0.5f * (Mm[i * kD + j] - Mm[j * kD + i]);
        }
    }

    // initial MLP h0 (accurate path)
    const float* x0 = x + (size_t)b * kT * kD;
    {
        float acc = bi0[t];
        #pragma unroll
        for (int k = 0; k < kD; k++) acc = fmaf(Wi0[t * kD + k], x0[k], acc);
        z0[t] = sp_f(acc);
    }
    __syncthreads();
    {
        float acc = bi1[t];
        #pragma unroll 16
        for (int k = 0; k < kH; k++) acc = fmaf(Wi1[t * kH + k], z0[k], acc);
        z1[t] = sp_f(acc);
    }
    __syncthreads();
    if (t < kS) {
        float acc = bi2[t];
        #pragma unroll 16
        for (int k = 0; k < kH; k++) acc = fmaf(Wi2[t * kH + k], z1[k], acc);
        g_h0[b * kS + t] = acc;
    }
}

// ============================== scan kernel ================================
__global__ __launch_bounds__(NT, 1) __cluster_dims__(CL, 1, 1)
void logncde_v14_kernel(
    const float* __restrict__ Wv0, const float* __restrict__ bv0,
    const float* __restrict__ Wv1, const float* __restrict__ bv1,
    const float* __restrict__ Wv2, const float* __restrict__ bv2,
    const float* __restrict__ Wr,  const float* __restrict__ br,
    float* __restrict__ out)
{
    extern __shared__ float sm[];
    cg::cluster_group cluster = cg::this_cluster();
    const int t    = threadIdx.x;
    const int rank = (int)cluster.block_rank();
    const int b    = blockIdx.x >> 2;
    const int d0g  = 2 * rank;
    const int og   = t & 31;     // output group: rows 4og..4og+3
    const int kg   = t >> 5;     // k-octant == warp id

    float* peer[CL - 1];
    #pragma unroll
    for (int p = 1; p < CL; p++)
        peer[p - 1] = cluster.map_shared_rank(sm, (rank + p) & (CL - 1));

    // ---- register weight tiles (v6 layout) ----
    float4 w0r[8], w1r[16], w2r[16];
    {
        const float4* W0 = (const float4*)Wv0;
        #pragma unroll
        for (int r = 0; r < 4; r++)
            #pragma unroll
            for (int j = 0; j < 2; j++)
                w0r[r * 2 + j] = W0[(4 * og + r) * 16 + kg * 2 + j];
        const float4* W1 = (const float4*)Wv1;
        #pragma unroll
        for (int r = 0; r < 4; r++)
            #pragma unroll
            for (int j = 0; j < 4; j++)
                w1r[r * 4 + j] = W1[(4 * og + r) * 32 + kg * 4 + j];
        const float4* W2 = (const float4*)Wv2;
        #pragma unroll
        for (int r = 0; r < 4; r++)
            #pragma unroll
            for (int j = 0; j < 4; j++)
                w2r[r * 4 + j] = W2[(kH * rank + 4 * og + r) * 32 + kg * 4 + j];
    }

    // ---- staging ----
    for (int i = t; i < kH; i += NT) {
        sm[OFF_BV0 + i]  = bv0[i];
        sm[OFF_BV1 + i]  = bv1[i];
        sm[OFF_BV2S + i] = bv2[kH * rank + i];
    }
    for (int i = t; i < kOut * kS; i += NT) sm[OFF_WR + i] = Wr[i];
    if (t < kOut) sm[OFF_BR + t] = br[t];
    {
        const float* src = &g_sigs[(size_t)b * kNW * 36];
        for (int i = t; i < kNW * 36; i += NT) sm[OFF_SIGS + i] = src[i];
    }
    if (t < kS) sm[OFF_HH + t] = g_h0[b * kS + t];
    __syncthreads();

    // ---- precompute C coefficients for all steps (this rank's channels) ----
    for (int i = t; i < kNW * 16; i += NT) {
        int n = i >> 4, j = i & 15;
        int dl = j >> 3, e = j & 7;
        int d = d0g + dl;
        const float* sgn = &sm[OFF_SIGS + n * 36];
        float v = 0.f;
        if (e < d)      v =  sgn[8 + pidx(e, d)];
        else if (e > d) v = -sgn[8 + pidx(d, e)];
        sm[OFF_CH + n * 16 + dl * 8 + e] = v;
    }

    cluster.sync();

    float4* part4 = (float4*)&sm[OFF_PART];

    // ============================ scan loop ============================
    for (int n = 0; n < kNW; n++) {

        // --- A: partials of z0 = Wv0 h
        {
            const float4* h4 = (const float4*)&sm[OFF_HH + n * kS];
            float4 a = make_float4(0.f, 0.f, 0.f, 0.f);
            #pragma unroll
            for (int j = 0; j < 2; j++) {
                float4 hv = h4[kg * 2 + j];
                a.x = dot4(w0r[0 * 2 + j], hv, a.x);
                a.y = dot4(w0r[1 * 2 + j], hv, a.y);
                a.z = dot4(w0r[2 * 2 + j], hv, a.z);
                a.w = dot4(w0r[3 * 2 + j], hv, a.w);
            }
            part4[kg * 32 + og] = a;
        }
        __syncthreads();
        if (t < kH) {
            float s = sm[OFF_BV0 + t];
            #pragma unroll
            for (int q = 0; q < 8; q++) s += sm[OFF_PART + q * kH + t];
            float z, d;
            sp_sg(s, z, d);
            sm[OFF_Z0 + t] = z; sm[OFF_D0 + t] = d;
        }
        __syncthreads();

        // --- B: partials of z1 = Wv1 z0
        {
            const float4* z4 = (const float4*)&sm[OFF_Z0];
            float4 a = make_float4(0.f, 0.f, 0.f, 0.f);
            #pragma unroll
            for (int j = 0; j < 4; j++) {
                float4 zv = z4[kg * 4 + j];
                a.x = dot4(w1r[0 * 4 + j], zv, a.x);
                a.y = dot4(w1r[1 * 4 + j], zv, a.y);
                a.z = dot4(w1r[2 * 4 + j], zv, a.z);
                a.w = dot4(w1r[3 * 4 + j], zv, a.w);
            }
            part4[kg * 32 + og] = a;
        }
        __syncthreads();
        if (t < kH) {
            float s = sm[OFF_BV1 + t];
            #pragma unroll
            for (int q = 0; q < 8; q++) s += sm[OFF_PART + q * kH + t];
            float z, d;
            sp_sg(s, z, d);
            sm[OFF_Z1 + t] = z; sm[OFF_D1 + t] = d;
        }
        __syncthreads();

        // --- C: partials of V slice = Wv2_slice z1
        {
            const float4* z4 = (const float4*)&sm[OFF_Z1];
            float4 a = make_float4(0.f, 0.f, 0.f, 0.f);
            #pragma unroll
            for (int j = 0; j < 4; j++) {
                float4 zv = z4[kg * 4 + j];
                a.x = dot4(w2r[0 * 4 + j], zv, a.x);
                a.y = dot4(w2r[1 * 4 + j], zv, a.y);
                a.z = dot4(w2r[2 * 4 + j], zv, a.z);
                a.w = dot4(w2r[3 * 4 + j], zv, a.w);
            }
            part4[kg * 32 + og] = a;
        }
        __syncthreads();
        if (t < kH) {
            float s = sm[OFF_BV2S + t];
            #pragma unroll
            for (int q = 0; q < 8; q++) s += sm[OFF_PART + q * kH + t];
            float v = tanh_ap(s);
            int vi = OFF_V + kH * rank + t;
            sm[vi] = v;
            sm[OFF_TDS + t] = 1.f - v * v;
            peer[0][vi] = v;
            peer[1][vi] = v;
            peer[2][vi] = v;
        }
        cluster.sync();   // V(n) gathered everywhere

        // --- D: tangents w_dl = sum_e C[dl,e] V_e (own 2 channels)
        if (t < kH) {
            int dl = t >> 6, a_ = t & 63;
            const float* cj = &sm[OFF_CH + n * 16 + dl * 8];
            float acc = 0.f;
            #pragma unroll
            for (int e = 0; e < kD; e++)
                acc = fmaf(cj[e], sm[OFF_V + e * kS + a_], acc);
            sm[OFF_WT + dl * kS + a_] = acc;
        }
        __syncthreads();

        // --- E: partials of q_c = Wv0 wt_c (2 channels)
        {
            const float4* wt4 = (const float4*)&sm[OFF_WT];
            float4 a0 = make_float4(0.f, 0.f, 0.f, 0.f);
            float4 a1 = make_float4(0.f, 0.f, 0.f, 0.f);
            #pragma unroll
            for (int j = 0; j < 2; j++) {
                float4 v0 = wt4[kg * 2 + j];
                float4 v1 = wt4[16 + kg * 2 + j];
                a0.x = dot4(w0r[0 * 2 + j], v0, a0.x);
                a0.y = dot4(w0r[1 * 2 + j], v0, a0.y);
                a0.z = dot4(w0r[2 * 2 + j], v0, a0.z);
                a0.w = dot4(w0r[3 * 2 + j], v0, a0.w);
                a1.x = dot4(w0r[0 * 2 + j], v1, a1.x);
                a1.y = dot4(w0r[1 * 2 + j], v1, a1.y);
                a1.z = dot4(w0r[2 * 2 + j], v1, a1.z);
                a1.w = dot4(w0r[3 * 2 + j], v1, a1.w);
            }
            part4[kg * 32 + og] = a0;
            part4[256 + kg * 32 + og] = a1;
        }
        __syncthreads();
        {   // pt_c = D0 .* q_c (all 256 threads)
            int dl = t >> 7, o = t & 127;
            float s = 0.f;
            #pragma unroll
            for (int q = 0; q < 8; q++)
                s += sm[OFF_PART + dl * 1024 + q * kH + o];
            sm[OFF_PT + dl * kH + o] = s * sm[OFF_D0 + o];
        }
        __syncthreads();

        // --- F: partials of u'_c = Wv1 pt_c (2 channels)
        {
            const float4* pt4 = (const float4*)&sm[OFF_PT];
            float4 a0 = make_float4(0.f, 0.f, 0.f, 0.f);
            float4 a1 = make_float4(0.f, 0.f, 0.f, 0.f);
            #pragma unroll
            for (int j = 0; j < 4; j++) {
                float4 v0 = pt4[kg * 4 + j];
                float4 v1 = pt4[32 + kg * 4 + j];
                a0.x = dot4(w1r[0 * 4 + j], v0, a0.x);
                a0.y = dot4(w1r[1 * 4 + j], v0, a0.y);
                a0.z = dot4(w1r[2 * 4 + j], v0, a0.z);
                a0.w = dot4(w1r[3 * 4 + j], v0, a0.w);
                a1.x = dot4(w1r[0 * 4 + j], v1, a1.x);
                a1.y = dot4(w1r[1 * 4 + j], v1, a1.y);
                a1.z = dot4(w1r[2 * 4 + j], v1, a1.z);
                a1.w = dot4(w1r[3 * 4 + j], v1, a1.w);
            }
            part4[kg * 32 + og] = a0;
            part4[256 + kg * 32 + og] = a1;
        }
        __syncthreads();
        {   // ut_c = D1 .* u'_c
            int dl = t >> 7, o = t & 127;
            float s = 0.f;
            #pragma unroll
            for (int q = 0; q < 8; q++)
                s += sm[OFF_PART + dl * 1024 + q * kH + o];
            sm[OFF_UT + dl * kH + o] = s * sm[OFF_D1 + o];
        }
        __syncthreads();

        // --- G: partials of r = Wv2_slice u_{dl(row)}
        {
            int dl = og >> 4;
            const float4* u4 = (const float4*)&sm[OFF_UT + dl * kH];
            float4 a = make_float4(0.f, 0.f, 0.f, 0.f);
            #pragma unroll
            for (int j = 0; j < 4; j++) {
                float4 uv = u4[kg * 4 + j];
                a.x = dot4(w2r[0 * 4 + j], uv, a.x);
                a.y = dot4(w2r[1 * 4 + j], uv, a.y);
                a.z = dot4(w2r[2 * 4 + j], uv, a.z);
                a.w = dot4(w2r[3 * 4 + j], uv, a.w);
            }
            part4[kg * 32 + og] = a;
        }
        __syncthreads();
        // G-reduce: TD, fold channels, ADD a.V(own channels), push to peers
        if (t < kS) {
            float s0 = 0.f, s1 = 0.f;
            #pragma unroll
            for (int q = 0; q < 8; q++) {
                s0 += sm[OFF_PART + q * kH + t];
                s1 += sm[OFF_PART + q * kH + kS + t];
            }
            const float* sgn = &sm[OFF_SIGS + n * 36];
            float rs = s0 * sm[OFF_TDS + t] + s1 * sm[OFF_TDS + kS + t]
                     + sgn[d0g]     * sm[OFF_V + d0g * kS + t]
                     + sgn[d0g + 1] * sm[OFF_V + (d0g + 1) * kS + t];
            int ri = OFF_RSLOT + kS * rank + t;
            sm[ri] = rs;
            peer[0][ri] = rs;
            peer[1][ri] = rs;
            peer[2][ri] = rs;
        }
        cluster.sync();   // corrections gathered everywhere

        // --- H: h_{n+1} = h_n + sum_p c_p
        if (t < kS) {
            float acc = sm[OFF_HH + n * kS + t];
            #pragma unroll
            for (int p = 0; p < CL; p++)
                acc += sm[OFF_RSLOT + p * kS + t];
            sm[OFF_HH + (n + 1) * kS + t] = acc;
        }
        __syncthreads();
    }

    // ---- readout of the full h history (rank 0, parallel GEMM) ----
    if (rank == 0) {
        for (int idx = t; idx < (kNW + 1) * kOut; idx += NT) {
            int n = idx >> 3, oo = idx & 7;
            float acc = sm[OFF_BR + oo];
            const float* hh = &sm[OFF_HH + n * kS];
            #pragma unroll 16
            for (int a = 0; a < kS; a++)
                acc = fmaf(sm[OFF_WR + oo * kS + a], hh[a], acc);
            out[((size_t)b * (kNW + 1) + n) * kOut + oo] = acc;
        }
    }
    cluster.sync();   // no CTA exits while peers may still touch its smem
}

extern "C" void kernel_launch(void* const* d_in, const int* in_sizes, int n_in,
                              void* d_out, int out_size) {
    // metadata order: ts, x, Wi0,bi0, Wi1,bi1, Wi2,bi2, Wv0,bv0, Wv1,bv1, Wv2,bv2, Wr,br
    const float* x   = (const float*)d_in[1];
    const float* Wi0 = (const float*)d_in[2];
    const float* bi0 = (const float*)d_in[3];
    const float* Wi1 = (const float*)d_in[4];
    const float* bi1 = (const float*)d_in[5];
    const float* Wi2 = (const float*)d_in[6];
    const float* bi2 = (const float*)d_in[7];
    const float* Wv0 = (const float*)d_in[8];
    const float* bv0 = (const float*)d_in[9];
    const float* Wv1 = (const float*)d_in[10];
    const float* bv1 = (const float*)d_in[11];
    const float* Wv2 = (const float*)d_in[12];
    const float* bv2 = (const float*)d_in[13];
    const float* Wr  = (const float*)d_in[14];
    const float* br  = (const float*)d_in[15];
    float* out = (float*)d_out;

    logncde_prep_kernel<<<kB, 128>>>(x, Wi0, bi0, Wi1, bi1, Wi2, bi2);

    cudaFuncSetAttribute(logncde_v14_kernel,
                         cudaFuncAttributeMaxDynamicSharedMemorySize,
                         SMEMF * (int)sizeof(float));
    logncde_v14_kernel<<<kB * CL, NT, SMEMF * sizeof(float)>>>(
        Wv0, bv0, Wv1, bv1, Wv2, bv2, Wr, br, out);
}

// round 15
// speedup vs baseline: 2.1795x; 1.0397x over previous
#include <cuda_runtime.h>
#include <cooperative_groups.h>
#include <math.h>
#include <stdint.h>

namespace cg = cooperative_groups;

// ---------------------------------------------------------------------------
// LogNCDE depth-2 log-ODE scan, 4-CTA cluster per batch element (128 CTAs).
// Rank r owns channels {2r,2r+1} and Wv2 rows [128r,128r+128).
// v15 = v14 scan kernel (register weight tiles 4 rows x k-octant, float4 smem
// partial trees, cluster.sync exchanges, precomputed C, fast activations,
// a.V folded into exchanged correction, hoisted readout) + PARALLEL prep:
// one thread per (batch,window) with float4 loads, h0 blocks alongside.
// ---------------------------------------------------------------------------

namespace {
constexpr int kB   = 32;
constexpr int kT   = 2049;
constexpr int kD   = 8;
constexpr int kS   = 64;
constexpr int kH   = 128;
constexpr int kP   = 28;
constexpr int kNW  = 128;
constexpr int kWin = 16;
constexpr int kOut = 8;
constexpr int CL   = 4;
constexpr int NT   = 256;
constexpr int SIGBLK = (kB * kNW) / 256;   // 16 sig blocks
constexpr int PREPBLK = SIGBLK + kB;       // + 32 h0 blocks = 48

// shared-memory float offsets (16B aligned)
constexpr int OFF_SIGS  = 0;        // [128][36]
constexpr int OFF_CH    = 4608;     // [128][16]
constexpr int OFF_BV0   = 6656;     // 128
constexpr int OFF_BV1   = 6784;     // 128
constexpr int OFF_BV2S  = 6912;     // 128
constexpr int OFF_WR    = 7040;     // 512
constexpr int OFF_BR    = 7552;     // 16
constexpr int OFF_HH    = 7568;     // [129][64]
constexpr int OFF_Z0    = 15824;    // 128
constexpr int OFF_D0    = 15952;    // 128
constexpr int OFF_Z1    = 16080;    // 128
constexpr int OFF_D1    = 16208;    // 128
constexpr int OFF_V     = 16336;    // 512 (single buffer)
constexpr int OFF_TDS   = 16848;    // 128
constexpr int OFF_WT    = 16976;    // 2 x 64
constexpr int OFF_PT    = 17104;    // 2 x 128
constexpr int OFF_UT    = 17360;    // 2 x 128
constexpr int OFF_RSLOT = 17616;    // 4 x 64
constexpr int OFF_PART  = 17872;    // 2 x 8 x 128 partials
constexpr int SMEMF     = 19920;    // ~80 KB
}  // namespace

__device__ float g_sigs[kB * kNW * 36];   // per-batch window signatures
__device__ float g_h0[kB * kS];           // per-batch initial state

static __device__ const int c_II[kP] =
    {0,0,0,0,0,0,0,1,1,1,1,1,1,2,2,2,2,2,3,3,3,3,4,4,4,5,5,6};
static __device__ const int c_JJ[kP] =
    {1,2,3,4,5,6,7,2,3,4,5,6,7,3,4,5,6,7,4,5,6,7,5,6,7,6,7,7};

__device__ __forceinline__ int pidx(int i, int j) {   // Lyndon pair index, i<j
    return 7 * i - (i * (i - 1)) / 2 + (j - i - 1);
}
__device__ __forceinline__ float dot4(float4 w, float4 v, float acc) {
    acc = fmaf(w.x, v.x, acc); acc = fmaf(w.y, v.y, acc);
    acc = fmaf(w.z, v.z, acc); acc = fmaf(w.w, v.w, acc);
    return acc;
}
__device__ __forceinline__ float tanh_ap(float x) {
    float r; asm("tanh.approx.f32 %0, %1;" : "=f"(r) : "f"(x)); return r;
}
__device__ __forceinline__ void sp_sg(float s, float& z, float& d) {
    if (s > 20.f) { z = s; d = 1.f; }
    else {
        float e = __expf(s);
        float inv = __frcp_rn(1.f + e);
        z = __logf(1.f + e);
        d = e * inv;
    }
}
__device__ __forceinline__ float sp_f(float x) {   // accurate (one-time h0)
    return (x > 20.f) ? x : log1pf(expf(x));
}

// ============ prep kernel: sigs (blocks 0..15) + h0 (blocks 16..47) ========
__global__ __launch_bounds__(256, 1)
void logncde_prep_kernel(
    const float* __restrict__ x,
    const float* __restrict__ Wi0, const float* __restrict__ bi0,
    const float* __restrict__ Wi1, const float* __restrict__ bi1,
    const float* __restrict__ Wi2, const float* __restrict__ bi2)
{
    __shared__ float z0s[kH], z1s[kH];
    const int blk = blockIdx.x;
    const int t = threadIdx.x;

    if (blk < SIGBLK) {
        // one thread per (batch, window); float4 loads, fully unrolled
        int g = blk * 256 + t;
        int b = g >> 7, win = g & 127;
        const float4* xb =
            (const float4*)(x + (size_t)b * kT * kD + (size_t)win * kWin * kD);
        float cum[kD], prev[kD], Mm[kD * kD];
        {
            float4 p0 = xb[0], p1 = xb[1];
            prev[0] = p0.x; prev[1] = p0.y; prev[2] = p0.z; prev[3] = p0.w;
            prev[4] = p1.x; prev[5] = p1.y; prev[6] = p1.z; prev[7] = p1.w;
        }
        #pragma unroll
        for (int i = 0; i < kD; i++) cum[i] = 0.f;
        #pragma unroll
        for (int i = 0; i < kD * kD; i++) Mm[i] = 0.f;
        #pragma unroll
        for (int w = 0; w < kWin; w++) {
            float4 c0 = xb[2 * (w + 1)], c1 = xb[2 * (w + 1) + 1];
            float cur[kD] = {c0.x, c0.y, c0.z, c0.w, c1.x, c1.y, c1.z, c1.w};
            float dl[kD];
            #pragma unroll
            for (int j = 0; j < kD; j++) {
                dl[j] = cur[j] - prev[j];
                prev[j] = cur[j];
            }
            #pragma unroll
            for (int i = 0; i < kD; i++)
                #pragma unroll
                for (int j = 0; j < kD; j++)
                    Mm[i * kD + j] = fmaf(cum[i], dl[j], Mm[i * kD + j]);
            #pragma unroll
            for (int i = 0; i < kD; i++) cum[i] += dl[i];
        }
        float* sgw = &g_sigs[((size_t)b * kNW + win) * 36];
        #pragma unroll
        for (int i = 0; i < kD; i++) sgw[i] = cum[i];
        #pragma unroll
        for (int p = 0; p < kP; p++) {
            int i = c_II[p], j = c_JJ[p];
            sgw[8 + p] = 0.5f * (Mm[i * kD + j] - Mm[j * kD + i]);
        }
    } else {
        // h0 for batch (blk - SIGBLK); threads 0..127 work, all hit barriers
        int b = blk - SIGBLK;
        const float* x0 = x + (size_t)b * kT * kD;
        if (t < kH) {
            float acc = bi0[t];
            #pragma unroll
            for (int k = 0; k < kD; k++) acc = fmaf(Wi0[t * kD + k], x0[k], acc);
            z0s[t] = sp_f(acc);
        }
        __syncthreads();
        if (t < kH) {
            float acc = bi1[t];
            #pragma unroll 16
            for (int k = 0; k < kH; k++) acc = fmaf(Wi1[t * kH + k], z0s[k], acc);
            z1s[t] = sp_f(acc);
        }
        __syncthreads();
        if (t < kS) {
            float acc = bi2[t];
            #pragma unroll 16
            for (int k = 0; k < kH; k++) acc = fmaf(Wi2[t * kH + k], z1s[k], acc);
            g_h0[b * kS + t] = acc;
        }
    }
}

// ============================== scan kernel ================================
__global__ __launch_bounds__(NT, 1) __cluster_dims__(CL, 1, 1)
void logncde_v15_kernel(
    const float* __restrict__ Wv0, const float* __restrict__ bv0,
    const float* __restrict__ Wv1, const float* __restrict__ bv1,
    const float* __restrict__ Wv2, const float* __restrict__ bv2,
    const float* __restrict__ Wr,  const float* __restrict__ br,
    float* __restrict__ out)
{
    extern __shared__ float sm[];
    cg::cluster_group cluster = cg::this_cluster();
    const int t    = threadIdx.x;
    const int rank = (int)cluster.block_rank();
    const int b    = blockIdx.x >> 2;
    const int d0g  = 2 * rank;
    const int og   = t & 31;     // output group: rows 4og..4og+3
    const int kg   = t >> 5;     // k-octant == warp id

    float* peer[CL - 1];
    #pragma unroll
    for (int p = 1; p < CL; p++)
        peer[p - 1] = cluster.map_shared_rank(sm, (rank + p) & (CL - 1));

    // ---- register weight tiles ----
    float4 w0r[8], w1r[16], w2r[16];
    {
        const float4* W0 = (const float4*)Wv0;
        #pragma unroll
        for (int r = 0; r < 4; r++)
            #pragma unroll
            for (int j = 0; j < 2; j++)
                w0r[r * 2 + j] = W0[(4 * og + r) * 16 + kg * 2 + j];
        const float4* W1 = (const float4*)Wv1;
        #pragma unroll
        for (int r = 0; r < 4; r++)
            #pragma unroll
            for (int j = 0; j < 4; j++)
                w1r[r * 4 + j] = W1[(4 * og + r) * 32 + kg * 4 + j];
        const float4* W2 = (const float4*)Wv2;
        #pragma unroll
        for (int r = 0; r < 4; r++)
            #pragma unroll
            for (int j = 0; j < 4; j++)
                w2r[r * 4 + j] = W2[(kH * rank + 4 * og + r) * 32 + kg * 4 + j];
    }

    // ---- staging ----
    for (int i = t; i < kH; i += NT) {
        sm[OFF_BV0 + i]  = bv0[i];
        sm[OFF_BV1 + i]  = bv1[i];
        sm[OFF_BV2S + i] = bv2[kH * rank + i];
    }
    for (int i = t; i < kOut * kS; i += NT) sm[OFF_WR + i] = Wr[i];
    if (t < kOut) sm[OFF_BR + t] = br[t];
    {
        const float* src = &g_sigs[(size_t)b * kNW * 36];
        for (int i = t; i < kNW * 36; i += NT) sm[OFF_SIGS + i] = src[i];
    }
    if (t < kS) sm[OFF_HH + t] = g_h0[b * kS + t];
    __syncthreads();

    // ---- precompute C coefficients for all steps (this rank's channels) ----
    for (int i = t; i < kNW * 16; i += NT) {
        int n = i >> 4, j = i & 15;
        int dl = j >> 3, e = j & 7;
        int d = d0g + dl;
        const float* sgn = &sm[OFF_SIGS + n * 36];
        float v = 0.f;
        if (e < d)      v =  sgn[8 + pidx(e, d)];
        else if (e > d) v = -sgn[8 + pidx(d, e)];
        sm[OFF_CH + n * 16 + dl * 8 + e] = v;
    }

    cluster.sync();

    float4* part4 = (float4*)&sm[OFF_PART];

    // ============================ scan loop ============================
    for (int n = 0; n < kNW; n++) {

        // --- A: partials of z0 = Wv0 h
        {
            const float4* h4 = (const float4*)&sm[OFF_HH + n * kS];
            float4 a = make_float4(0.f, 0.f, 0.f, 0.f);
            #pragma unroll
            for (int j = 0; j < 2; j++) {
                float4 hv = h4[kg * 2 + j];
                a.x = dot4(w0r[0 * 2 + j], hv, a.x);
                a.y = dot4(w0r[1 * 2 + j], hv, a.y);
                a.z = dot4(w0r[2 * 2 + j], hv, a.z);
                a.w = dot4(w0r[3 * 2 + j], hv, a.w);
            }
            part4[kg * 32 + og] = a;
        }
        __syncthreads();
        if (t < kH) {
            float s = sm[OFF_BV0 + t];
            #pragma unroll
            for (int q = 0; q < 8; q++) s += sm[OFF_PART + q * kH + t];
            float z, d;
            sp_sg(s, z, d);
            sm[OFF_Z0 + t] = z; sm[OFF_D0 + t] = d;
        }
        __syncthreads();

        // --- B: partials of z1 = Wv1 z0
        {
            const float4* z4 = (const float4*)&sm[OFF_Z0];
            float4 a = make_float4(0.f, 0.f, 0.f, 0.f);
            #pragma unroll
            for (int j = 0; j < 4; j++) {
                float4 zv = z4[kg * 4 + j];
                a.x = dot4(w1r[0 * 4 + j], zv, a.x);
                a.y = dot4(w1r[1 * 4 + j], zv, a.y);
                a.z = dot4(w1r[2 * 4 + j], zv, a.z);
                a.w = dot4(w1r[3 * 4 + j], zv, a.w);
            }
            part4[kg * 32 + og] = a;
        }
        __syncthreads();
        if (t < kH) {
            float s = sm[OFF_BV1 + t];
            #pragma unroll
            for (int q = 0; q < 8; q++) s += sm[OFF_PART + q * kH + t];
            float z, d;
            sp_sg(s, z, d);
            sm[OFF_Z1 + t] = z; sm[OFF_D1 + t] = d;
        }
        __syncthreads();

        // --- C: partials of V slice = Wv2_slice z1
        {
            const float4* z4 = (const float4*)&sm[OFF_Z1];
            float4 a = make_float4(0.f, 0.f, 0.f, 0.f);
            #pragma unroll
            for (int j = 0; j < 4; j++) {
                float4 zv = z4[kg * 4 + j];
                a.x = dot4(w2r[0 * 4 + j], zv, a.x);
                a.y = dot4(w2r[1 * 4 + j], zv, a.y);
                a.z = dot4(w2r[2 * 4 + j], zv, a.z);
                a.w = dot4(w2r[3 * 4 + j], zv, a.w);
            }
            part4[kg * 32 + og] = a;
        }
        __syncthreads();
        if (t < kH) {
            float s = sm[OFF_BV2S + t];
            #pragma unroll
            for (int q = 0; q < 8; q++) s += sm[OFF_PART + q * kH + t];
            float v = tanh_ap(s);
            int vi = OFF_V + kH * rank + t;
            sm[vi] = v;
            sm[OFF_TDS + t] = 1.f - v * v;
            peer[0][vi] = v;
            peer[1][vi] = v;
            peer[2][vi] = v;
        }
        cluster.sync();   // V(n) gathered everywhere

        // --- D: tangents w_dl = sum_e C[dl,e] V_e (own 2 channels)
        if (t < kH) {
            int dl = t >> 6, a_ = t & 63;
            const float* cj = &sm[OFF_CH + n * 16 + dl * 8];
            float acc = 0.f;
            #pragma unroll
            for (int e = 0; e < kD; e++)
                acc = fmaf(cj[e], sm[OFF_V + e * kS + a_], acc);
            sm[OFF_WT + dl * kS + a_] = acc;
        }
        __syncthreads();

        // --- E: partials of q_c = Wv0 wt_c (2 channels)
        {
            const float4* wt4 = (const float4*)&sm[OFF_WT];
            float4 a0 = make_float4(0.f, 0.f, 0.f, 0.f);
            float4 a1 = make_float4(0.f, 0.f, 0.f, 0.f);
            #pragma unroll
            for (int j = 0; j < 2; j++) {
                float4 v0 = wt4[kg * 2 + j];
                float4 v1 = wt4[16 + kg * 2 + j];
                a0.x = dot4(w0r[0 * 2 + j], v0, a0.x);
                a0.y = dot4(w0r[1 * 2 + j], v0, a0.y);
                a0.z = dot4(w0r[2 * 2 + j], v0, a0.z);
                a0.w = dot4(w0r[3 * 2 + j], v0, a0.w);
                a1.x = dot4(w0r[0 * 2 + j], v1, a1.x);
                a1.y = dot4(w0r[1 * 2 + j], v1, a1.y);
                a1.z = dot4(w0r[2 * 2 + j], v1, a1.z);
                a1.w = dot4(w0r[3 * 2 + j], v1, a1.w);
            }
            part4[kg * 32 + og] = a0;
            part4[256 + kg * 32 + og] = a1;
        }
        __syncthreads();
        {   // pt_c = D0 .* q_c (all 256 threads)
            int dl = t >> 7, o = t & 127;
            float s = 0.f;
            #pragma unroll
            for (int q = 0; q < 8; q++)
                s += sm[OFF_PART + dl * 1024 + q * kH + o];
            sm[OFF_PT + dl * kH + o] = s * sm[OFF_D0 + o];
        }
        __syncthreads();

        // --- F: partials of u'_c = Wv1 pt_c (2 channels)
        {
            const float4* pt4 = (const float4*)&sm[OFF_PT];
            float4 a0 = make_float4(0.f, 0.f, 0.f, 0.f);
            float4 a1 = make_float4(0.f, 0.f, 0.f, 0.f);
            #pragma unroll
            for (int j = 0; j < 4; j++) {
                float4 v0 = pt4[kg * 4 + j];
                float4 v1 = pt4[32 + kg * 4 + j];
                a0.x = dot4(w1r[0 * 4 + j], v0, a0.x);
                a0.y = dot4(w1r[1 * 4 + j], v0, a0.y);
                a0.z = dot4(w1r[2 * 4 + j], v0, a0.z);
                a0.w = dot4(w1r[3 * 4 + j], v0, a0.w);
                a1.x = dot4(w1r[0 * 4 + j], v1, a1.x);
                a1.y = dot4(w1r[1 * 4 + j], v1, a1.y);
                a1.z = dot4(w1r[2 * 4 + j], v1, a1.z);
                a1.w = dot4(w1r[3 * 4 + j], v1, a1.w);
            }
            part4[kg * 32 + og] = a0;
            part4[256 + kg * 32 + og] = a1;
        }
        __syncthreads();
        {   // ut_c = D1 .* u'_c
            int dl = t >> 7, o = t & 127;
            float s = 0.f;
            #pragma unroll
            for (int q = 0; q < 8; q++)
                s += sm[OFF_PART + dl * 1024 + q * kH + o];
            sm[OFF_UT + dl * kH + o] = s * sm[OFF_D1 + o];
        }
        __syncthreads();

        // --- G: partials of r = Wv2_slice u_{dl(row)}
        {
            int dl = og >> 4;
            const float4* u4 = (const float4*)&sm[OFF_UT + dl * kH];
            float4 a = make_float4(0.f, 0.f, 0.f, 0.f);
            #pragma unroll
            for (int j = 0; j < 4; j++) {
                float4 uv = u4[kg * 4 + j];
                a.x = dot4(w2r[0 * 4 + j], uv, a.x);
                a.y = dot4(w2r[1 * 4 + j], uv, a.y);
                a.z = dot4(w2r[2 * 4 + j], uv, a.z);
                a.w = dot4(w2r[3 * 4 + j], uv, a.w);
            }
            part4[kg * 32 + og] = a;
        }
        __syncthreads();
        // G-reduce: TD, fold channels, add a.V(own channels), push to peers
        if (t < kS) {
            float s0 = 0.f, s1 = 0.f;
            #pragma unroll
            for (int q = 0; q < 8; q++) {
                s0 += sm[OFF_PART + q * kH + t];
                s1 += sm[OFF_PART + q * kH + kS + t];
            }
            const float* sgn = &sm[OFF_SIGS + n * 36];
            float rs = s0 * sm[OFF_TDS + t] + s1 * sm[OFF_TDS + kS + t]
                     + sgn[d0g]     * sm[OFF_V + d0g * kS + t]
                     + sgn[d0g + 1] * sm[OFF_V + (d0g + 1) * kS + t];
            int ri = OFF_RSLOT + kS * rank + t;
            sm[ri] = rs;
            peer[0][ri] = rs;
            peer[1][ri] = rs;
            peer[2][ri] = rs;
        }
        cluster.sync();   // corrections gathered everywhere

        // --- H: h_{n+1} = h_n + sum_p c_p
        if (t < kS) {
            float acc = sm[OFF_HH + n * kS + t];
            #pragma unroll
            for (int p = 0; p < CL; p++)
                acc += sm[OFF_RSLOT + p * kS + t];
            sm[OFF_HH + (n + 1) * kS + t] = acc;
        }
        __syncthreads();
    }

    // ---- readout of the full h history (rank 0, parallel GEMM) ----
    if (rank == 0) {
        for (int idx = t; idx < (kNW + 1) * kOut; idx += NT) {
            int n = idx >> 3, oo = idx & 7;
            float acc = sm[OFF_BR + oo];
            const float* hh = &sm[OFF_HH + n * kS];
            #pragma unroll 16
            for (int a = 0; a < kS; a++)
                acc = fmaf(sm[OFF_WR + oo * kS + a], hh[a], acc);
            out[((size_t)b * (kNW + 1) + n) * kOut + oo] = acc;
        }
    }
    cluster.sync();   // no CTA exits while peers may still touch its smem
}

extern "C" void kernel_launch(void* const* d_in, const int* in_sizes, int n_in,
                              void* d_out, int out_size) {
    // metadata order: ts, x, Wi0,bi0, Wi1,bi1, Wi2,bi2, Wv0,bv0, Wv1,bv1, Wv2,bv2, Wr,br
    const float* x   = (const float*)d_in[1];
    const float* Wi0 = (const float*)d_in[2];
    const float* bi0 = (const float*)d_in[3];
    const float* Wi1 = (const float*)d_in[4];
    const float* bi1 = (const float*)d_in[5];
    const float* Wi2 = (const float*)d_in[6];
    const float* bi2 = (const float*)d_in[7];
    const float* Wv0 = (const float*)d_in[8];
    const float* bv0 = (const float*)d_in[9];
    const float* Wv1 = (const float*)d_in[10];
    const float* bv1 = (const float*)d_in[11];
    const float* Wv2 = (const float*)d_in[12];
    const float* bv2 = (const float*)d_in[13];
    const float* Wr  = (const float*)d_in[14];
    const float* br  = (const float*)d_in[15];
    float* out = (float*)d_out;

    logncde_prep_kernel<<<PREPBLK, 256>>>(x, Wi0, bi0, Wi1, bi1, Wi2, bi2);

    cudaFuncSetAttribute(logncde_v15_kernel,
                         cudaFuncAttributeMaxDynamicSharedMemorySize,
                         SMEMF * (int)sizeof(float));
    logncde_v15_kernel<<<kB * CL, NT, SMEMF * sizeof(float)>>>(
        Wv0, bv0, Wv1, bv1, Wv2, bv2, Wr, br, out);
}